// round 1
// baseline (speedup 1.0000x reference)
#include <cuda_runtime.h>
#include <cstdint>

// Problem constants (fixed by the dataset)
#define BB    4
#define NBC   128
#define NINT  4096
#define HID   64

// Scratch (device globals: allocation-free)
__device__ float g_avec[BB * NBC * HID];      // a = bf @ G0w[:64]           (32K floats)
__device__ float g_cbT[BB * HID * NINT];      // cbT[b][k][i] = c + G0b      (1M floats)
__device__ float g_partial[4 * BB * NINT];    // per-nbc-chunk partial sums  (64K floats)

typedef unsigned long long ull;

__device__ __forceinline__ ull pack2(float x, float y) {
    ull r;
    asm("mov.b64 %0, {%1, %2};" : "=l"(r) : "f"(x), "f"(y));
    return r;
}
__device__ __forceinline__ void unpack2(ull v, float& x, float& y) {
    asm("mov.b64 {%0, %1}, %2;" : "=f"(x), "=f"(y) : "l"(v));
}
__device__ __forceinline__ void fma2(ull& d, ull a, ull b, ull c) {
    asm("fma.rn.f32x2 %0, %1, %2, %3;" : "=l"(d) : "l"(a), "l"(b), "l"(c));
}

// ---------------------------------------------------------------------------
// Prep A: per (b,nbc): bf = relu(relu(binfo@W0+b0)@W1+b1);  avec = bf @ G0w[:64]
// grid = B*NBC blocks, 64 threads
// ---------------------------------------------------------------------------
__global__ void prepA_kernel(const float* __restrict__ binfo,
                             const float* __restrict__ W0, const float* __restrict__ b0,
                             const float* __restrict__ W1, const float* __restrict__ b1,
                             const float* __restrict__ G0w) {
    __shared__ float bf0[HID];
    __shared__ float bf1[HID];
    int bn = blockIdx.x;            // 0..511  (b*128 + nbc)
    int j  = threadIdx.x;           // 0..63

    const float* bi = binfo + bn * 3;
    float x0 = bi[0], x1 = bi[1], x2 = bi[2];
    bf0[j] = fmaxf(fmaf(x0, W0[j], fmaf(x1, W0[64 + j], fmaf(x2, W0[128 + j], b0[j]))), 0.0f);
    __syncthreads();

    float s = b1[j];
    #pragma unroll 8
    for (int k = 0; k < HID; k++) s = fmaf(bf0[k], W1[k * 64 + j], s);
    bf1[j] = fmaxf(s, 0.0f);
    __syncthreads();

    float a = 0.0f;
    #pragma unroll 8
    for (int k = 0; k < HID; k++) a = fmaf(bf1[k], G0w[k * 64 + j], a);
    g_avec[bn * 64 + j] = a;
}

// ---------------------------------------------------------------------------
// Prep B: cbT[b][j][i] = coords[b][i][0]*G0w[64][j] + coords[b][i][1]*G0w[65][j] + G0b[j]
// grid = (64, 4), 256 threads
// ---------------------------------------------------------------------------
__global__ void prepB_kernel(const float* __restrict__ coords,
                             const float* __restrict__ G0w,
                             const float* __restrict__ G0b) {
    int j = blockIdx.x;             // hidden dim 0..63
    int b = blockIdx.y;             // batch
    float wx = G0w[64 * 64 + j];
    float wy = G0w[65 * 64 + j];
    float bb = G0b[j];
    const float* cb = coords + (size_t)b * NINT * 2;
    float* dst = g_cbT + ((size_t)b * HID + j) * NINT;
    for (int i = threadIdx.x; i < NINT; i += blockDim.x) {
        float cx = cb[i * 2 + 0];
        float cy = cb[i * 2 + 1];
        dst[i] = fmaf(cx, wx, fmaf(cy, wy, bb));
    }
}

// ---------------------------------------------------------------------------
// Main fused kernel.
// grid = (16 tiles, 4 batch, 4 nbc-chunks), 128 threads.
// Each thread owns 2 interior rows x all 64 h2 columns (64 packed f32x2 accs).
// For each of 32 nbc in its chunk: h1[k] computed on the fly, packed FMA2
// against G1w rows (broadcast LDS), then relu + G2 dot in registers.
// ---------------------------------------------------------------------------
#define ITILE   256
#define THREADS 128
#define NBC_CHK 32

// dynamic smem layout (floats):
//   s_w   [64*64]      G1w row-major
//   s_cbT [64*256]     cbT tile (row k, col = local interior idx)
//   s_a   [32*64]      avec rows for this nbc chunk
//   s_g1b [64], s_g2w [64]
#define SMEM_FLOATS (64*64 + 64*ITILE + NBC_CHK*64 + 64 + 64)

__global__ void __launch_bounds__(THREADS)
main_kernel(const float* __restrict__ G1w,
            const float* __restrict__ G1b,
            const float* __restrict__ G2w) {
    extern __shared__ float smem[];
    float* s_w   = smem;                    // 4096
    float* s_cbT = s_w + 64 * 64;           // 16384
    float* s_a   = s_cbT + 64 * ITILE;      // 2048
    float* s_g1b = s_a + NBC_CHK * 64;      // 64
    float* s_g2w = s_g1b + 64;              // 64

    const int tid   = threadIdx.x;
    const int tile  = blockIdx.x;   // 0..15
    const int b     = blockIdx.y;   // 0..3
    const int chunk = blockIdx.z;   // 0..3
    const int i0g   = tile * ITILE; // global interior base of this tile

    // --- cooperative loads ---
    // G1w: 4096 floats, float4
    {
        const float4* src = reinterpret_cast<const float4*>(G1w);
        float4* dst = reinterpret_cast<float4*>(s_w);
        for (int i = tid; i < 1024; i += THREADS) dst[i] = src[i];
    }
    // cbT tile: 64 rows x 256 cols
    {
        for (int idx = tid; idx < 64 * 64; idx += THREADS) {
            int k  = idx >> 6;
            int c4 = idx & 63;
            const float4* src = reinterpret_cast<const float4*>(
                g_cbT + ((size_t)b * HID + k) * NINT + i0g) + c4;
            reinterpret_cast<float4*>(s_cbT + k * ITILE)[c4] = *src;
        }
    }
    // avec rows for this chunk: 32 x 64 contiguous
    {
        const float4* src = reinterpret_cast<const float4*>(
            g_avec + ((size_t)b * NBC + chunk * NBC_CHK) * 64);
        float4* dst = reinterpret_cast<float4*>(s_a);
        for (int i = tid; i < NBC_CHK * 16; i += THREADS) dst[i] = src[i];
    }
    if (tid < 64) { s_g1b[tid] = G1b[tid]; s_g2w[tid] = G2w[tid]; }
    __syncthreads();

    const int lc = 2 * tid;         // local column (interior idx) for row pair

    float accOut0 = 0.0f, accOut1 = 0.0f;

    for (int nn = 0; nn < NBC_CHK; nn++) {
        ull acc0[32], acc1[32];
        #pragma unroll
        for (int j = 0; j < 32; j++) { acc0[j] = 0ull; acc1[j] = 0ull; }

        const float* aptr = s_a + nn * 64;
        #pragma unroll 4
        for (int k = 0; k < 64; k++) {
            float ak = aptr[k];
            float2 cb = *reinterpret_cast<const float2*>(s_cbT + k * ITILE + lc);
            float h0 = fmaxf(ak + cb.x, 0.0f);
            float h1 = fmaxf(ak + cb.y, 0.0f);
            ull h0p = pack2(h0, h0);
            ull h1p = pack2(h1, h1);
            const float* wrow = s_w + k * 64;
            #pragma unroll
            for (int j = 0; j < 32; j++) {
                ull wp = *reinterpret_cast<const ull*>(wrow + 2 * j);
                fma2(acc0[j], h0p, wp, acc0[j]);
                fma2(acc1[j], h1p, wp, acc1[j]);
            }
        }

        // epilogue: h2 = relu(acc + g1b); contribution += h2 . g2w
        float s0 = 0.0f, s1 = 0.0f;
        #pragma unroll
        for (int j = 0; j < 32; j++) {
            float v0x, v0y, v1x, v1y;
            unpack2(acc0[j], v0x, v0y);
            unpack2(acc1[j], v1x, v1y);
            float bx = s_g1b[2 * j], by = s_g1b[2 * j + 1];
            float wx = s_g2w[2 * j], wy = s_g2w[2 * j + 1];
            s0 = fmaf(fmaxf(v0x + bx, 0.0f), wx, s0);
            s0 = fmaf(fmaxf(v0y + by, 0.0f), wy, s0);
            s1 = fmaf(fmaxf(v1x + bx, 0.0f), wx, s1);
            s1 = fmaf(fmaxf(v1y + by, 0.0f), wy, s1);
        }
        accOut0 += s0;
        accOut1 += s1;
    }

    float* dst = g_partial + ((size_t)chunk * BB + b) * NINT + i0g + lc;
    dst[0] = accOut0;
    dst[1] = accOut1;
}

// ---------------------------------------------------------------------------
// Final reduction: out[b][i] = (sum over 4 chunks) / NBC + G2b
// ---------------------------------------------------------------------------
__global__ void final_kernel(const float* __restrict__ G2b, float* __restrict__ out) {
    int idx = blockIdx.x * blockDim.x + threadIdx.x;   // 0..16383
    if (idx >= BB * NINT) return;
    int b  = idx / NINT;
    int ii = idx % NINT;
    float s = 0.0f;
    #pragma unroll
    for (int ch = 0; ch < 4; ch++)
        s += g_partial[((size_t)ch * BB + b) * NINT + ii];
    out[idx] = s * (1.0f / (float)NBC) + G2b[0];
}

// ---------------------------------------------------------------------------
// Launch
// Inputs (metadata order):
// 0 boundary_info 1 interior_coords 2 W0 3 b0 4 W1 5 b1
// 6 G0w 7 G0b 8 G1w 9 G1b 10 G2w 11 G2b 12 interior_h 13 interior_w
// ---------------------------------------------------------------------------
extern "C" void kernel_launch(void* const* d_in, const int* in_sizes, int n_in,
                              void* d_out, int out_size) {
    const float* binfo  = (const float*)d_in[0];
    const float* coords = (const float*)d_in[1];
    const float* W0     = (const float*)d_in[2];
    const float* b0     = (const float*)d_in[3];
    const float* W1     = (const float*)d_in[4];
    const float* b1     = (const float*)d_in[5];
    const float* G0w    = (const float*)d_in[6];
    const float* G0b    = (const float*)d_in[7];
    const float* G1w    = (const float*)d_in[8];
    const float* G1b    = (const float*)d_in[9];
    const float* G2w    = (const float*)d_in[10];
    const float* G2b    = (const float*)d_in[11];
    float* out          = (float*)d_out;

    const int smem_bytes = SMEM_FLOATS * (int)sizeof(float);   // ~90.6 KB
    cudaFuncSetAttribute(main_kernel, cudaFuncAttributeMaxDynamicSharedMemorySize, smem_bytes);

    prepA_kernel<<<BB * NBC, 64>>>(binfo, W0, b0, W1, b1, G0w);
    prepB_kernel<<<dim3(HID, BB), 256>>>(coords, G0w, G0b);
    main_kernel<<<dim3(NINT / ITILE, BB, 4), THREADS, smem_bytes>>>(G1w, G1b, G2w);
    final_kernel<<<(BB * NINT + 255) / 256, 256>>>(G2b, out);
}

// round 2
// speedup vs baseline: 1.8316x; 1.8316x over previous
#include <cuda_runtime.h>
#include <cstdint>

// Problem constants (fixed by the dataset)
#define BB    4
#define NBC   128
#define NINT  4096
#define HID   64

#define ROWS_PB  128      // interior rows per block
#define THREADS  128
#define NBC_PB   8        // boundary points per block (16 chunks)
#define NCHUNK   (NBC / NBC_PB)

// Scratch (device globals: allocation-free)
__device__ float g_avec[BB * NBC * HID];          // a = bf @ G0w[:64]
__device__ float g_cbT[BB * HID * NINT];          // cbT[b][k][i]
__device__ float g_partial[NCHUNK * BB * NINT];   // per-chunk partial sums

typedef unsigned long long ull;

__device__ __forceinline__ ull pack2(float x, float y) {
    ull r;
    asm("mov.b64 %0, {%1, %2};" : "=l"(r) : "f"(x), "f"(y));
    return r;
}
__device__ __forceinline__ void unpack2(ull v, float& x, float& y) {
    asm("mov.b64 {%0, %1}, %2;" : "=f"(x), "=f"(y) : "l"(v));
}
__device__ __forceinline__ void fma2(ull& d, ull a, ull b, ull c) {
    asm("fma.rn.f32x2 %0, %1, %2, %3;" : "=l"(d) : "l"(a), "l"(b), "l"(c));
}

// ---------------------------------------------------------------------------
// Prep A: per (b,nbc): bf = relu(relu(binfo@W0+b0)@W1+b1);  avec = bf @ G0w[:64]
// ---------------------------------------------------------------------------
__global__ void prepA_kernel(const float* __restrict__ binfo,
                             const float* __restrict__ W0, const float* __restrict__ b0,
                             const float* __restrict__ W1, const float* __restrict__ b1,
                             const float* __restrict__ G0w) {
    __shared__ float bf0[HID];
    __shared__ float bf1[HID];
    int bn = blockIdx.x;            // 0..511
    int j  = threadIdx.x;           // 0..63

    const float* bi = binfo + bn * 3;
    float x0 = bi[0], x1 = bi[1], x2 = bi[2];
    bf0[j] = fmaxf(fmaf(x0, W0[j], fmaf(x1, W0[64 + j], fmaf(x2, W0[128 + j], b0[j]))), 0.0f);
    __syncthreads();

    float s = b1[j];
    #pragma unroll 8
    for (int k = 0; k < HID; k++) s = fmaf(bf0[k], W1[k * 64 + j], s);
    bf1[j] = fmaxf(s, 0.0f);
    __syncthreads();

    float a = 0.0f;
    #pragma unroll 8
    for (int k = 0; k < HID; k++) a = fmaf(bf1[k], G0w[k * 64 + j], a);
    g_avec[bn * 64 + j] = a;
}

// ---------------------------------------------------------------------------
// Prep B: cbT[b][j][i] = cx*G0w[64][j] + cy*G0w[65][j] + G0b[j]
// ---------------------------------------------------------------------------
__global__ void prepB_kernel(const float* __restrict__ coords,
                             const float* __restrict__ G0w,
                             const float* __restrict__ G0b) {
    int j = blockIdx.x;
    int b = blockIdx.y;
    float wx = G0w[64 * 64 + j];
    float wy = G0w[65 * 64 + j];
    float bb = G0b[j];
    const float* cb = coords + (size_t)b * NINT * 2;
    float* dst = g_cbT + ((size_t)b * HID + j) * NINT;
    for (int i = threadIdx.x; i < NINT; i += blockDim.x) {
        float cx = cb[i * 2 + 0];
        float cy = cb[i * 2 + 1];
        dst[i] = fmaf(cx, wx, fmaf(cy, wy, bb));
    }
}

// ---------------------------------------------------------------------------
// Main fused kernel.
// grid = (32 row-blocks, 4 batch, 16 nbc-chunks), 128 threads.
// Thread layout: colgroup cg = tid>>5 (16 cols), rowgroup rg = tid&31 (4 rows).
// Accumulators: 4 rows x 8 col-pairs packed f32x2, initialized with G1b.
// ---------------------------------------------------------------------------

// dynamic smem (floats):
#define SW_OFF   0                       // G1w          64*64  = 4096
#define SC_OFF   (SW_OFF + 64 * 64)      // cbT tile     64*128 = 8192
#define SA_OFF   (SC_OFF + 64 * ROWS_PB) // avec rows    8*64   = 512
#define SB_OFF   (SA_OFF + NBC_PB * 64)  // G1b          64
#define SG_OFF   (SB_OFF + 64)           // G2w          64
#define SR_OFF   (SG_OFF + 64)           // reduction    4*128  = 512
#define SMEM_FLOATS (SR_OFF + 4 * ROWS_PB)

__global__ void __launch_bounds__(THREADS, 3)
main_kernel(const float* __restrict__ G1w,
            const float* __restrict__ G1b,
            const float* __restrict__ G2w) {
    extern __shared__ float smem[];
    float* s_w   = smem + SW_OFF;
    float* s_cbT = smem + SC_OFF;
    float* s_a   = smem + SA_OFF;
    float* s_g1b = smem + SB_OFF;
    float* s_g2w = smem + SG_OFF;
    float* s_red = smem + SR_OFF;

    const int tid   = threadIdx.x;
    const int rb    = blockIdx.x;                 // row-block 0..31
    const int b     = blockIdx.y;                 // batch
    const int chunk = blockIdx.z;                 // nbc chunk 0..15
    const int i0g   = rb * ROWS_PB;

    // --- cooperative loads ---
    {   // G1w: 4096 floats
        const float4* src = reinterpret_cast<const float4*>(G1w);
        float4* dst = reinterpret_cast<float4*>(s_w);
        #pragma unroll
        for (int i = tid; i < 1024; i += THREADS) dst[i] = src[i];
    }
    {   // cbT tile: 64 rows(k) x 128 cols(rows)
        #pragma unroll
        for (int idx = tid; idx < 64 * 32; idx += THREADS) {
            int k  = idx >> 5;
            int c4 = idx & 31;
            const float4* src = reinterpret_cast<const float4*>(
                g_cbT + ((size_t)b * HID + k) * NINT + i0g) + c4;
            reinterpret_cast<float4*>(s_cbT + k * ROWS_PB)[c4] = *src;
        }
    }
    {   // avec rows for this chunk: 8 x 64
        const float4* src = reinterpret_cast<const float4*>(
            g_avec + ((size_t)b * NBC + chunk * NBC_PB) * 64);
        float4* dst = reinterpret_cast<float4*>(s_a);
        if (tid < NBC_PB * 16) dst[tid] = src[tid];
    }
    if (tid < 64) { s_g1b[tid] = G1b[tid]; s_g2w[tid] = G2w[tid]; }
    __syncthreads();

    const int cg = tid >> 5;      // colgroup 0..3 -> cols [cg*16, cg*16+16)
    const int rg = tid & 31;      // rowgroup -> rows [rg*4, rg*4+4)
    const int j0 = cg * 16;
    const int r0 = rg * 4;

    // loop-invariant epilogue constants in registers
    ull bp[8];
    float wv[16];
    #pragma unroll
    for (int p = 0; p < 8; p++)
        bp[p] = *reinterpret_cast<const ull*>(s_g1b + j0 + 2 * p);
    #pragma unroll
    for (int jj = 0; jj < 16; jj++) wv[jj] = s_g2w[j0 + jj];

    float out0 = 0.0f, out1 = 0.0f, out2 = 0.0f, out3 = 0.0f;

    for (int nn = 0; nn < NBC_PB; nn++) {
        ull acc[4][8];
        #pragma unroll
        for (int r = 0; r < 4; r++)
            #pragma unroll
            for (int p = 0; p < 8; p++) acc[r][p] = bp[p];

        const float* aptr = s_a + nn * 64;
        #pragma unroll 8
        for (int k = 0; k < 64; k++) {
            float ak = aptr[k];                                        // broadcast
            float4 c = *reinterpret_cast<const float4*>(s_cbT + k * ROWS_PB + r0);
            float h0 = fmaxf(ak + c.x, 0.0f);
            float h1 = fmaxf(ak + c.y, 0.0f);
            float h2 = fmaxf(ak + c.z, 0.0f);
            float h3 = fmaxf(ak + c.w, 0.0f);
            ull h0p = pack2(h0, h0);
            ull h1p = pack2(h1, h1);
            ull h2p = pack2(h2, h2);
            ull h3p = pack2(h3, h3);
            const float* wrow = s_w + k * 64 + j0;
            #pragma unroll
            for (int p = 0; p < 8; p++) {
                ull wp = *reinterpret_cast<const ull*>(wrow + 2 * p);  // broadcast
                fma2(acc[0][p], h0p, wp, acc[0][p]);
                fma2(acc[1][p], h1p, wp, acc[1][p]);
                fma2(acc[2][p], h2p, wp, acc[2][p]);
                fma2(acc[3][p], h3p, wp, acc[3][p]);
            }
        }

        // epilogue: out[r] += sum_j relu(acc) * g2w
        #pragma unroll
        for (int p = 0; p < 8; p++) {
            float lo, hi;
            float wlo = wv[2 * p], whi = wv[2 * p + 1];
            unpack2(acc[0][p], lo, hi);
            out0 = fmaf(fmaxf(lo, 0.0f), wlo, out0);
            out0 = fmaf(fmaxf(hi, 0.0f), whi, out0);
            unpack2(acc[1][p], lo, hi);
            out1 = fmaf(fmaxf(lo, 0.0f), wlo, out1);
            out1 = fmaf(fmaxf(hi, 0.0f), whi, out1);
            unpack2(acc[2][p], lo, hi);
            out2 = fmaf(fmaxf(lo, 0.0f), wlo, out2);
            out2 = fmaf(fmaxf(hi, 0.0f), whi, out2);
            unpack2(acc[3][p], lo, hi);
            out3 = fmaf(fmaxf(lo, 0.0f), wlo, out3);
            out3 = fmaf(fmaxf(hi, 0.0f), whi, out3);
        }
    }

    // cross-colgroup reduction via smem
    s_red[cg * ROWS_PB + r0 + 0] = out0;   // first colgroup writes...
    __syncthreads();                        // (all write their own slice)
    s_red[cg * ROWS_PB + r0 + 1] = out1;
    s_red[cg * ROWS_PB + r0 + 2] = out2;
    s_red[cg * ROWS_PB + r0 + 3] = out3;
    __syncthreads();

    // 128 threads: one row each
    {
        int row = tid;
        float s = s_red[0 * ROWS_PB + row] + s_red[1 * ROWS_PB + row]
                + s_red[2 * ROWS_PB + row] + s_red[3 * ROWS_PB + row];
        g_partial[((size_t)chunk * BB + b) * NINT + i0g + row] = s;
    }
}

// ---------------------------------------------------------------------------
// Final reduction: out[b][i] = (sum over chunks) / NBC + G2b
// ---------------------------------------------------------------------------
__global__ void final_kernel(const float* __restrict__ G2b, float* __restrict__ out) {
    int idx = blockIdx.x * blockDim.x + threadIdx.x;
    if (idx >= BB * NINT) return;
    int b  = idx / NINT;
    int ii = idx % NINT;
    float s = 0.0f;
    #pragma unroll
    for (int ch = 0; ch < NCHUNK; ch++)
        s += g_partial[((size_t)ch * BB + b) * NINT + ii];
    out[idx] = s * (1.0f / (float)NBC) + G2b[0];
}

// ---------------------------------------------------------------------------
// Launch.  Inputs (metadata order):
// 0 boundary_info 1 interior_coords 2 W0 3 b0 4 W1 5 b1
// 6 G0w 7 G0b 8 G1w 9 G1b 10 G2w 11 G2b 12 interior_h 13 interior_w
// ---------------------------------------------------------------------------
extern "C" void kernel_launch(void* const* d_in, const int* in_sizes, int n_in,
                              void* d_out, int out_size) {
    const float* binfo  = (const float*)d_in[0];
    const float* coords = (const float*)d_in[1];
    const float* W0     = (const float*)d_in[2];
    const float* b0     = (const float*)d_in[3];
    const float* W1     = (const float*)d_in[4];
    const float* b1     = (const float*)d_in[5];
    const float* G0w    = (const float*)d_in[6];
    const float* G0b    = (const float*)d_in[7];
    const float* G1w    = (const float*)d_in[8];
    const float* G1b    = (const float*)d_in[9];
    const float* G2w    = (const float*)d_in[10];
    const float* G2b    = (const float*)d_in[11];
    float* out          = (float*)d_out;

    const int smem_bytes = SMEM_FLOATS * (int)sizeof(float);   // ~53.8 KB
    cudaFuncSetAttribute(main_kernel, cudaFuncAttributeMaxDynamicSharedMemorySize, smem_bytes);

    prepA_kernel<<<BB * NBC, 64>>>(binfo, W0, b0, W1, b1, G0w);
    prepB_kernel<<<dim3(HID, BB), 256>>>(coords, G0w, G0b);
    main_kernel<<<dim3(NINT / ROWS_PB, BB, NCHUNK), THREADS, smem_bytes>>>(G1w, G1b, G2w);
    final_kernel<<<(BB * NINT + 255) / 256, 256>>>(G2b, out);
}

// round 4
// speedup vs baseline: 3.0078x; 1.6422x over previous
#include <cuda_runtime.h>
#include <cstdint>

// Problem constants (fixed by the dataset)
#define BB    4
#define NBC   128
#define NINT  4096
#define HID   64

// ---------------------------------------------------------------------------
// Device scratch (allocation-free)
// ---------------------------------------------------------------------------
__device__ float g_avec[BB * NBC * HID];              // a[b][nbc][k]
__device__ float g_c[BB * NINT * HID];                // c[b][i][k] (incl. G0b)

// ---------------------------------------------------------------------------
// tf32 helpers (plain sm_80+ instructions — legal on sm_103 without 'a')
// ---------------------------------------------------------------------------
__device__ __forceinline__ uint32_t cvt_tf32(float x) {
    uint32_t r;
    asm("cvt.rna.tf32.f32 %0, %1;" : "=r"(r) : "f"(x));
    return r;
}

__device__ __forceinline__ void mma_tf32(float& d0, float& d1, float& d2, float& d3,
                                         uint32_t a0, uint32_t a1, uint32_t a2, uint32_t a3,
                                         uint32_t b0, uint32_t b1) {
    asm volatile("mma.sync.aligned.m16n8k8.row.col.f32.tf32.tf32.f32 "
                 "{%0,%1,%2,%3}, {%4,%5,%6,%7}, {%8,%9}, {%0,%1,%2,%3};"
                 : "+f"(d0), "+f"(d1), "+f"(d2), "+f"(d3)
                 : "r"(a0), "r"(a1), "r"(a2), "r"(a3), "r"(b0), "r"(b1));
}

// ---------------------------------------------------------------------------
// Prep A: per (b,nbc): bf = relu(relu(binfo@W0+b0)@W1+b1);  a = bf @ G0w[:64]
// ---------------------------------------------------------------------------
__global__ void prepA_kernel(const float* __restrict__ binfo,
                             const float* __restrict__ W0, const float* __restrict__ b0,
                             const float* __restrict__ W1, const float* __restrict__ b1,
                             const float* __restrict__ G0w) {
    __shared__ float bf0[HID];
    __shared__ float bf1[HID];
    int bn = blockIdx.x;            // 0..511
    int j  = threadIdx.x;           // 0..63
    const float* bi = binfo + bn * 3;
    float x0 = bi[0], x1 = bi[1], x2 = bi[2];
    bf0[j] = fmaxf(fmaf(x0, W0[j], fmaf(x1, W0[64 + j], fmaf(x2, W0[128 + j], b0[j]))), 0.0f);
    __syncthreads();
    float s = b1[j];
    #pragma unroll 8
    for (int k = 0; k < HID; k++) s = fmaf(bf0[k], W1[k * 64 + j], s);
    bf1[j] = fmaxf(s, 0.0f);
    __syncthreads();
    float a = 0.0f;
    #pragma unroll 8
    for (int k = 0; k < HID; k++) a = fmaf(bf1[k], G0w[k * 64 + j], a);
    g_avec[bn * 64 + j] = a;
}

// ---------------------------------------------------------------------------
// Prep C: c[b][i][k] = cx*G0w[64][k] + cy*G0w[65][k] + G0b[k]   (i-major)
// ---------------------------------------------------------------------------
__global__ void prepC_kernel(const float* __restrict__ coords,
                             const float* __restrict__ G0w,
                             const float* __restrict__ G0b) {
    __shared__ float swx[HID], swy[HID], sgb[HID];
    int t = threadIdx.x;
    if (t < HID) { swx[t] = G0w[64 * 64 + t]; swy[t] = G0w[65 * 64 + t]; sgb[t] = G0b[t]; }
    __syncthreads();
    int r = blockIdx.x * 128 + t;          // 0..16383
    float cx = coords[(size_t)r * 2 + 0];
    float cy = coords[(size_t)r * 2 + 1];
    float* dst = g_c + (size_t)r * HID;
    #pragma unroll
    for (int kg = 0; kg < 16; kg++) {
        float4 v;
        v.x = fmaf(cx, swx[kg * 4 + 0], fmaf(cy, swy[kg * 4 + 0], sgb[kg * 4 + 0]));
        v.y = fmaf(cx, swx[kg * 4 + 1], fmaf(cy, swy[kg * 4 + 1], sgb[kg * 4 + 1]));
        v.z = fmaf(cx, swx[kg * 4 + 2], fmaf(cy, swy[kg * 4 + 2], sgb[kg * 4 + 2]));
        v.w = fmaf(cx, swx[kg * 4 + 3], fmaf(cy, swy[kg * 4 + 3], sgb[kg * 4 + 3]));
        reinterpret_cast<float4*>(dst)[kg] = v;
    }
}

// ---------------------------------------------------------------------------
// Main kernel.
// grid (32 tiles, 4 batch), 256 threads = 8 warps, each warp one m16 row-block.
// Per nbc iteration:
//   A-frags (h1, tf32) built in registers from a[nn] (smem bcast) + c (regs).
//   B-frags (G1w hi/lo interleaved uint2, smem, conflict-free stride 68).
//   D per n-block in 4 regs; epilogue relu(d+g1b)*g2w folded into 2 accums.
// ---------------------------------------------------------------------------
#define WSTRIDE 68   // uint2 units per k-row: banks = 8*tig + 2*gid, conflict-free

// dynamic smem: s_a 8192 floats (32768B) + s_w 64*68 uint2 (34816B)
#define SMEM_A_BYTES 32768
#define SMEM_TOTAL   (SMEM_A_BYTES + 64 * WSTRIDE * 8)

__global__ void __launch_bounds__(256, 1)
main_kernel(const float* __restrict__ G1w,
            const float* __restrict__ G1b,
            const float* __restrict__ G2w,
            const float* __restrict__ G2b,
            float* __restrict__ out) {
    extern __shared__ char smem[];
    float* s_a = reinterpret_cast<float*>(smem);
    uint2* s_w = reinterpret_cast<uint2*>(smem + SMEM_A_BYTES);

    const int tid  = threadIdx.x;
    const int wid  = tid >> 5;
    const int lane = tid & 31;
    const int gid  = lane >> 2;     // 0..7
    const int tig  = lane & 3;      // 0..3
    const int tile = blockIdx.x;    // 0..31
    const int b    = blockIdx.y;    // 0..3
    const int row0 = b * NINT + tile * 128 + wid * 16 + gid;   // global row (i)

    // --- cooperative smem init ---
    {   // a for this batch: 8192 floats
        const float4* src = reinterpret_cast<const float4*>(g_avec + (size_t)b * NBC * HID);
        float4* dst = reinterpret_cast<float4*>(s_a);
        #pragma unroll
        for (int i = tid; i < 2048; i += 256) dst[i] = src[i];
    }
    {   // G1w hi/lo split, interleaved uint2, padded stride
        #pragma unroll
        for (int idx = tid; idx < HID * HID; idx += 256) {
            int k = idx >> 6, j = idx & 63;
            float w  = G1w[idx];
            uint32_t hi = cvt_tf32(w);
            float    hf = __uint_as_float(hi);        // tf32 pattern is a valid f32
            uint32_t lo = cvt_tf32(w - hf);
            s_w[k * WSTRIDE + j] = make_uint2(hi, lo);
        }
    }

    // --- loop-invariant registers ---
    float c0r[16], c1r[16];                 // c for rows (row0) and (row0+8)
    {
        const float* cr0 = g_c + (size_t)row0 * HID;
        const float* cr1 = g_c + (size_t)(row0 + 8) * HID;
        #pragma unroll
        for (int s = 0; s < 8; s++) {
            c0r[2 * s + 0] = cr0[8 * s + tig];
            c0r[2 * s + 1] = cr0[8 * s + tig + 4];
            c1r[2 * s + 0] = cr1[8 * s + tig];
            c1r[2 * s + 1] = cr1[8 * s + tig + 4];
        }
    }
    float g1bv[16], g2wv[16];               // per-thread j = nb*8 + 2*tig + h
    #pragma unroll
    for (int nb = 0; nb < 8; nb++) {
        int j = nb * 8 + 2 * tig;
        g1bv[2 * nb + 0] = G1b[j];     g1bv[2 * nb + 1] = G1b[j + 1];
        g2wv[2 * nb + 0] = G2w[j];     g2wv[2 * nb + 1] = G2w[j + 1];
    }
    __syncthreads();

    float acc0 = 0.0f, acc1 = 0.0f;

    for (int nn = 0; nn < NBC; nn++) {
        const float* arow = s_a + nn * 64;

        // Build A fragments: h1 = relu(a + c), rna-rounded to tf32.
        uint32_t af[8][4];
        #pragma unroll
        for (int s = 0; s < 8; s++) {
            float av0 = arow[8 * s + tig];
            float av4 = arow[8 * s + tig + 4];
            af[s][0] = cvt_tf32(fmaxf(av0 + c0r[2 * s + 0], 0.0f));   // (row gid,   k)
            af[s][1] = cvt_tf32(fmaxf(av0 + c1r[2 * s + 0], 0.0f));   // (row gid+8, k)
            af[s][2] = cvt_tf32(fmaxf(av4 + c0r[2 * s + 1], 0.0f));   // (row gid,   k+4)
            af[s][3] = cvt_tf32(fmaxf(av4 + c1r[2 * s + 1], 0.0f));   // (row gid+8, k+4)
        }

        #pragma unroll
        for (int nb = 0; nb < 8; nb++) {
            float d0 = 0.0f, d1 = 0.0f, d2 = 0.0f, d3 = 0.0f;
            const int col = nb * 8 + gid;
            #pragma unroll
            for (int s = 0; s < 8; s++) {
                uint2 p = s_w[(8 * s + tig) * WSTRIDE + col];        // rows k
                uint2 q = s_w[(8 * s + tig + 4) * WSTRIDE + col];    // rows k+4
                mma_tf32(d0, d1, d2, d3, af[s][0], af[s][1], af[s][2], af[s][3], p.x, q.x);
                mma_tf32(d0, d1, d2, d3, af[s][0], af[s][1], af[s][2], af[s][3], p.y, q.y);
            }
            // epilogue: u[i] += relu(h2 + g1b) * g2w
            float b0 = g1bv[2 * nb], b1 = g1bv[2 * nb + 1];
            float w0 = g2wv[2 * nb], w1 = g2wv[2 * nb + 1];
            acc0 = fmaf(fmaxf(d0 + b0, 0.0f), w0, acc0);
            acc0 = fmaf(fmaxf(d1 + b1, 0.0f), w1, acc0);
            acc1 = fmaf(fmaxf(d2 + b0, 0.0f), w0, acc1);
            acc1 = fmaf(fmaxf(d3 + b1, 0.0f), w1, acc1);
        }
    }

    // reduce over the 4 tig lanes (each holds a disjoint j-subset for same i)
    acc0 += __shfl_xor_sync(0xFFFFFFFFu, acc0, 1);
    acc0 += __shfl_xor_sync(0xFFFFFFFFu, acc0, 2);
    acc1 += __shfl_xor_sync(0xFFFFFFFFu, acc1, 1);
    acc1 += __shfl_xor_sync(0xFFFFFFFFu, acc1, 2);

    if (tig == 0) {
        float g2 = G2b[0];
        out[row0]     = acc0 * (1.0f / (float)NBC) + g2;
        out[row0 + 8] = acc1 * (1.0f / (float)NBC) + g2;
    }
}

// ---------------------------------------------------------------------------
// Launch.  Inputs (metadata order):
// 0 boundary_info 1 interior_coords 2 W0 3 b0 4 W1 5 b1
// 6 G0w 7 G0b 8 G1w 9 G1b 10 G2w 11 G2b 12 interior_h 13 interior_w
// ---------------------------------------------------------------------------
extern "C" void kernel_launch(void* const* d_in, const int* in_sizes, int n_in,
                              void* d_out, int out_size) {
    const float* binfo  = (const float*)d_in[0];
    const float* coords = (const float*)d_in[1];
    const float* W0     = (const float*)d_in[2];
    const float* b0     = (const float*)d_in[3];
    const float* W1     = (const float*)d_in[4];
    const float* b1     = (const float*)d_in[5];
    const float* G0w    = (const float*)d_in[6];
    const float* G0b    = (const float*)d_in[7];
    const float* G1w    = (const float*)d_in[8];
    const float* G1b    = (const float*)d_in[9];
    const float* G2w    = (const float*)d_in[10];
    const float* G2b    = (const float*)d_in[11];
    float* out          = (float*)d_out;

    cudaFuncSetAttribute(main_kernel, cudaFuncAttributeMaxDynamicSharedMemorySize, SMEM_TOTAL);

    prepA_kernel<<<BB * NBC, 64>>>(binfo, W0, b0, W1, b1, G0w);
    prepC_kernel<<<BB * NINT / 128, 128>>>(coords, G0w, G0b);
    main_kernel<<<dim3(32, BB), 256, SMEM_TOTAL>>>(G1w, G1b, G2w, G2b, out);
}

// round 5
// speedup vs baseline: 5.6553x; 1.8802x over previous
#include <cuda_runtime.h>
#include <cstdint>

// Problem constants (fixed by the dataset)
#define BB    4
#define NBC   128
#define NINT  4096
#define HID   64

// ---------------------------------------------------------------------------
// Device scratch (allocation-free)
// ---------------------------------------------------------------------------
__device__ float g_avec[BB * NBC * HID];              // a[b][nbc][k]
__device__ float g_c[BB * NINT * HID];                // c[b][i][k] (incl. G0b)

// ---------------------------------------------------------------------------
// tf32 helpers (plain sm_80+ instructions — legal on sm_103 without 'a')
// ---------------------------------------------------------------------------
__device__ __forceinline__ uint32_t cvt_tf32(float x) {
    uint32_t r;
    asm("cvt.rna.tf32.f32 %0, %1;" : "=r"(r) : "f"(x));
    return r;
}

__device__ __forceinline__ void mma_tf32(float& d0, float& d1, float& d2, float& d3,
                                         uint32_t a0, uint32_t a1, uint32_t a2, uint32_t a3,
                                         uint32_t b0, uint32_t b1) {
    asm volatile("mma.sync.aligned.m16n8k8.row.col.f32.tf32.tf32.f32 "
                 "{%0,%1,%2,%3}, {%4,%5,%6,%7}, {%8,%9}, {%0,%1,%2,%3};"
                 : "+f"(d0), "+f"(d1), "+f"(d2), "+f"(d3)
                 : "r"(a0), "r"(a1), "r"(a2), "r"(a3), "r"(b0), "r"(b1));
}

// ---------------------------------------------------------------------------
// Merged prep kernel, 128 threads per block.
//  blocks [0, 256):  prepA — 2 boundary points per block
//  blocks [256, 384): prepC — 128 interior rows per block
// ---------------------------------------------------------------------------
__global__ void __launch_bounds__(128)
prep_kernel(const float* __restrict__ binfo,
            const float* __restrict__ W0, const float* __restrict__ b0,
            const float* __restrict__ W1, const float* __restrict__ b1,
            const float* __restrict__ G0w, const float* __restrict__ G0b,
            const float* __restrict__ coords) {
    __shared__ float sh[2][2][HID];     // [stage][sub][j]
    const int tid = threadIdx.x;

    if (blockIdx.x < 256) {
        // ---- prepA: bf = relu(relu(binfo@W0+b0)@W1+b1);  a = bf @ G0w[:64]
        const int sub = tid >> 6;       // 0..1
        const int j   = tid & 63;
        const int bn  = blockIdx.x * 2 + sub;    // 0..511
        const float* bi = binfo + bn * 3;
        float x0 = bi[0], x1 = bi[1], x2 = bi[2];
        sh[0][sub][j] = fmaxf(
            fmaf(x0, W0[j], fmaf(x1, W0[64 + j], fmaf(x2, W0[128 + j], b0[j]))), 0.0f);
        __syncthreads();
        float s = b1[j];
        #pragma unroll 8
        for (int k = 0; k < HID; k++) s = fmaf(sh[0][sub][k], W1[k * 64 + j], s);
        sh[1][sub][j] = fmaxf(s, 0.0f);
        __syncthreads();
        float a = 0.0f;
        #pragma unroll 8
        for (int k = 0; k < HID; k++) a = fmaf(sh[1][sub][k], G0w[k * 64 + j], a);
        g_avec[bn * 64 + j] = a;
    } else {
        // ---- prepC: c[r][k] = cx*G0w[64][k] + cy*G0w[65][k] + G0b[k]
        float* swx = sh[0][0];          // reuse shared
        float* swy = sh[0][1];
        float* sgb = sh[1][0];
        if (tid < HID) {
            swx[tid] = G0w[64 * 64 + tid];
            swy[tid] = G0w[65 * 64 + tid];
            sgb[tid] = G0b[tid];
        }
        __syncthreads();
        int r = (blockIdx.x - 256) * 128 + tid;    // 0..16383
        float cx = coords[(size_t)r * 2 + 0];
        float cy = coords[(size_t)r * 2 + 1];
        float* dst = g_c + (size_t)r * HID;
        #pragma unroll
        for (int kg = 0; kg < 16; kg++) {
            float4 v;
            v.x = fmaf(cx, swx[kg * 4 + 0], fmaf(cy, swy[kg * 4 + 0], sgb[kg * 4 + 0]));
            v.y = fmaf(cx, swx[kg * 4 + 1], fmaf(cy, swy[kg * 4 + 1], sgb[kg * 4 + 1]));
            v.z = fmaf(cx, swx[kg * 4 + 2], fmaf(cy, swy[kg * 4 + 2], sgb[kg * 4 + 2]));
            v.w = fmaf(cx, swx[kg * 4 + 3], fmaf(cy, swy[kg * 4 + 3], sgb[kg * 4 + 3]));
            reinterpret_cast<float4*>(dst)[kg] = v;
        }
    }
}

// ---------------------------------------------------------------------------
// Main kernel.
// grid (32 tiles, 4 batch), 256 threads = 8 warps, each warp one m16 row-block.
// Single-pass tf32 (weights rna-rounded; unbiased error ~2^-12 cancels over
// the 8192-term output sum — measured margin from round 4 supports this).
// B packed as uint2{W[k][j], W[k+4][j]}: one LDS.64 feeds one MMA.
// ---------------------------------------------------------------------------
#define WSTRIDE 68   // uint2 units per packed k-row; banks 8*tig+2*gid, conflict-free per phase

// dynamic smem: s_a 8192 floats (32768B) + s_w 32*68 uint2 (17408B)
#define SMEM_A_BYTES 32768
#define SMEM_TOTAL   (SMEM_A_BYTES + 32 * WSTRIDE * 8)

__global__ void __launch_bounds__(256, 1)
main_kernel(const float* __restrict__ G1w,
            const float* __restrict__ G1b,
            const float* __restrict__ G2w,
            const float* __restrict__ G2b,
            float* __restrict__ out) {
    extern __shared__ char smem[];
    float* s_a = reinterpret_cast<float*>(smem);
    uint2* s_w = reinterpret_cast<uint2*>(smem + SMEM_A_BYTES);

    const int tid  = threadIdx.x;
    const int wid  = tid >> 5;
    const int lane = tid & 31;
    const int gid  = lane >> 2;     // 0..7
    const int tig  = lane & 3;      // 0..3
    const int tile = blockIdx.x;    // 0..31
    const int b    = blockIdx.y;    // 0..3
    const int row0 = b * NINT + tile * 128 + wid * 16 + gid;   // global row (i)

    // --- cooperative smem init ---
    {   // a for this batch: 8192 floats
        const float4* src = reinterpret_cast<const float4*>(g_avec + (size_t)b * NBC * HID);
        float4* dst = reinterpret_cast<float4*>(s_a);
        #pragma unroll
        for (int i = tid; i < 2048; i += 256) dst[i] = src[i];
    }
    {   // G1w tf32 hi, packed pairs (k, k+4) per (s,tig) row
        #pragma unroll
        for (int idx = tid; idx < 32 * 64; idx += 256) {
            int prow = idx >> 6;            // 0..31  = s*4 + tig
            int col  = idx & 63;
            int s    = prow >> 2;
            int tg   = prow & 3;
            int k0   = 8 * s + tg;
            uint32_t w0 = cvt_tf32(G1w[k0 * 64 + col]);
            uint32_t w1 = cvt_tf32(G1w[(k0 + 4) * 64 + col]);
            s_w[prow * WSTRIDE + col] = make_uint2(w0, w1);
        }
    }

    // --- loop-invariant registers ---
    float c0r[16], c1r[16];                 // c for rows (row0) and (row0+8)
    {
        const float* cr0 = g_c + (size_t)row0 * HID;
        const float* cr1 = g_c + (size_t)(row0 + 8) * HID;
        #pragma unroll
        for (int s = 0; s < 8; s++) {
            c0r[2 * s + 0] = cr0[8 * s + tig];
            c0r[2 * s + 1] = cr0[8 * s + tig + 4];
            c1r[2 * s + 0] = cr1[8 * s + tig];
            c1r[2 * s + 1] = cr1[8 * s + tig + 4];
        }
    }
    float g1bv[16], g2wv[16];               // per-thread j = nb*8 + 2*tig + h
    #pragma unroll
    for (int nb = 0; nb < 8; nb++) {
        int j = nb * 8 + 2 * tig;
        g1bv[2 * nb + 0] = G1b[j];     g1bv[2 * nb + 1] = G1b[j + 1];
        g2wv[2 * nb + 0] = G2w[j];     g2wv[2 * nb + 1] = G2w[j + 1];
    }
    __syncthreads();

    float acc0 = 0.0f, acc1 = 0.0f;

    for (int nn = 0; nn < NBC; nn++) {
        const float* arow = s_a + nn * 64;

        // Build A fragments: h1 = relu(a + c), rna-rounded to tf32.
        uint32_t af[8][4];
        #pragma unroll
        for (int s = 0; s < 8; s++) {
            float av0 = arow[8 * s + tig];
            float av4 = arow[8 * s + tig + 4];
            af[s][0] = cvt_tf32(fmaxf(av0 + c0r[2 * s + 0], 0.0f));   // (row gid,   k)
            af[s][1] = cvt_tf32(fmaxf(av0 + c1r[2 * s + 0], 0.0f));   // (row gid+8, k)
            af[s][2] = cvt_tf32(fmaxf(av4 + c0r[2 * s + 1], 0.0f));   // (row gid,   k+4)
            af[s][3] = cvt_tf32(fmaxf(av4 + c1r[2 * s + 1], 0.0f));   // (row gid+8, k+4)
        }

        #pragma unroll
        for (int nb = 0; nb < 8; nb++) {
            float d0 = 0.0f, d1 = 0.0f, d2 = 0.0f, d3 = 0.0f;
            const int col = nb * 8 + gid;
            #pragma unroll
            for (int s = 0; s < 8; s++) {
                uint2 p = s_w[(s * 4 + tig) * WSTRIDE + col];   // {W[k], W[k+4]}
                mma_tf32(d0, d1, d2, d3, af[s][0], af[s][1], af[s][2], af[s][3], p.x, p.y);
            }
            // epilogue: u[i] += relu(h2 + g1b) * g2w
            float b0 = g1bv[2 * nb], b1 = g1bv[2 * nb + 1];
            float w0 = g2wv[2 * nb], w1 = g2wv[2 * nb + 1];
            acc0 = fmaf(fmaxf(d0 + b0, 0.0f), w0, acc0);
            acc0 = fmaf(fmaxf(d1 + b1, 0.0f), w1, acc0);
            acc1 = fmaf(fmaxf(d2 + b0, 0.0f), w0, acc1);
            acc1 = fmaf(fmaxf(d3 + b1, 0.0f), w1, acc1);
        }
    }

    // reduce over the 4 tig lanes (each holds a disjoint j-subset for same i)
    acc0 += __shfl_xor_sync(0xFFFFFFFFu, acc0, 1);
    acc0 += __shfl_xor_sync(0xFFFFFFFFu, acc0, 2);
    acc1 += __shfl_xor_sync(0xFFFFFFFFu, acc1, 1);
    acc1 += __shfl_xor_sync(0xFFFFFFFFu, acc1, 2);

    if (tig == 0) {
        float g2 = G2b[0];
        out[row0]     = acc0 * (1.0f / (float)NBC) + g2;
        out[row0 + 8] = acc1 * (1.0f / (float)NBC) + g2;
    }
}

// ---------------------------------------------------------------------------
// Launch.  Inputs (metadata order):
// 0 boundary_info 1 interior_coords 2 W0 3 b0 4 W1 5 b1
// 6 G0w 7 G0b 8 G1w 9 G1b 10 G2w 11 G2b 12 interior_h 13 interior_w
// ---------------------------------------------------------------------------
extern "C" void kernel_launch(void* const* d_in, const int* in_sizes, int n_in,
                              void* d_out, int out_size) {
    const float* binfo  = (const float*)d_in[0];
    const float* coords = (const float*)d_in[1];
    const float* W0     = (const float*)d_in[2];
    const float* b0     = (const float*)d_in[3];
    const float* W1     = (const float*)d_in[4];
    const float* b1     = (const float*)d_in[5];
    const float* G0w    = (const float*)d_in[6];
    const float* G0b    = (const float*)d_in[7];
    const float* G1w    = (const float*)d_in[8];
    const float* G1b    = (const float*)d_in[9];
    const float* G2w    = (const float*)d_in[10];
    const float* G2b    = (const float*)d_in[11];
    float* out          = (float*)d_out;

    cudaFuncSetAttribute(main_kernel, cudaFuncAttributeMaxDynamicSharedMemorySize, SMEM_TOTAL);

    prep_kernel<<<384, 128>>>(binfo, W0, b0, W1, b1, G0w, G0b, coords);
    main_kernel<<<dim3(32, BB), 256, SMEM_TOTAL>>>(G1w, G1b, G2w, G2b, out);
}